// round 9
// baseline (speedup 1.0000x reference)
#include <cuda_runtime.h>

// QuantumSelfAttention — FINAL (locked config, 3rd+ reproduction).
//
// The reference computes softmax(z, axis=-1).mean(axis=-1): softmax rows sum
// to exactly 1, so the mean over that same axis is identically 1/4 for every
// sample. The entire quantum circuit (RX/RY/RZ/CNOT statevector evolution and
// Z expectations) is dead code w.r.t. the output. Output = 0.25 everywhere;
// measured rel_err 4.1e-8 vs the fp32 reference.
//
// out_size = 2048*256 = 524288 floats (2 MiB, fully L2-resident).
// Launch-floor bound: ~0.2us of real store work inside a ~3.85us kernel
// (DRAM 0%, L2 ~5%, issue ~10%). Eight-round sweep results:
//   128x1024 STG.128 x1 -> kernel 3.84-3.94us, totals 5.06/5.09/5.31 (BEST)
//   512x256  STG.128 x1 -> 3.81 / 5.15
//   256x512  STG.128 x1 -> 3.81 / 5.89(noise)
//   128x256  STG.128 x4 -> 4.29 (store depth regresses)
//   64x1024  STG.256 x1 -> 4.29 (wavefronts don't halve; chip under-spanned)
// Total-time variance (5.06..6.34us on identical kernel SASS) is harness
// replay overhead, outside the kernel contract. Axes closed: algorithm
// (constant fold), store width, grid shape. This is the floor.

__global__ void __launch_bounds__(1024, 1)
qsa_fill_exact_kernel(float4* __restrict__ out4) {
    out4[blockIdx.x * 1024 + threadIdx.x] =
        make_float4(0.25f, 0.25f, 0.25f, 0.25f);
}

// General fallbacks (not launched for this problem's out_size; kept for safety).
__global__ void qsa_fill_stride_kernel(float4* __restrict__ out4, int n4) {
    const float4 v = make_float4(0.25f, 0.25f, 0.25f, 0.25f);
    int idx = blockIdx.x * blockDim.x + threadIdx.x;
    int stride = gridDim.x * blockDim.x;
    for (int i = idx; i < n4; i += stride) out4[i] = v;
}
__global__ void qsa_fill_tail_kernel(float* __restrict__ out, int start, int n) {
    int i = start + blockIdx.x * blockDim.x + threadIdx.x;
    if (i < n) out[i] = 0.25f;
}

extern "C" void kernel_launch(void* const* d_in, const int* in_sizes, int n_in,
                              void* d_out, int out_size) {
    (void)d_in; (void)in_sizes; (void)n_in;

    float* out = (float*)d_out;
    int n4 = out_size >> 2;

    if ((out_size & 3) == 0 && (n4 & 1023) == 0) {
        // Exact cover: one float4 per thread, 1024 threads/block.
        // out_size=524288 -> n4=131072 -> 128 blocks.
        qsa_fill_exact_kernel<<<n4 / 1024, 1024>>>((float4*)out);
    } else {
        if (n4 > 0) {
            int blocks = (n4 + 255) / 256;
            if (blocks > 16384) blocks = 16384;
            qsa_fill_stride_kernel<<<blocks, 256>>>((float4*)out, n4);
        }
        int tail_start = n4 << 2;
        if (tail_start < out_size) {
            int rem = out_size - tail_start;
            qsa_fill_tail_kernel<<<(rem + 255) / 256, 256>>>(out, tail_start, out_size);
        }
    }
}

// round 10
// speedup vs baseline: 1.1720x; 1.1720x over previous
#include <cuda_runtime.h>

// QuantumSelfAttention — FINAL (locked config).
//
// Reference tail: softmax(z, axis=-1).mean(axis=-1). Softmax rows sum to
// exactly 1, so the mean over that axis is identically 1/4 for every sample;
// the entire quantum circuit (RX/RY/RZ/CNOT statevector + Z expectations) is
// dead code w.r.t. the output. Output = 0.25 everywhere (rel_err 4.1e-8).
//
// out_size = 524288 floats (2 MiB, L2-resident). Launch-floor bound:
// kernel deterministic at 3.85±0.05us (~= T_ovh floor) with ~0.2us real
// store work; totals {5.06, 5.09, 5.31, 5.89} on identical SASS = harness
// replay jitter. Nine-round sweep closed all axes:
//   128x1024 STG.128 x1 -> 3.84-3.94us kernel, best totals (LOCKED)
//   512x256 / 256x512 STG.128 x1 -> tie on kernel, worse/noisier totals
//   128x256 STG.128 x4 -> +0.45us (per-thread depth regresses)
//   64x1024 STG.256 x1 -> +0.45us (wavefronts don't halve; chip under-spanned)
// DRAM 0%, L2 ~5%, issue ~10% -> no chip resource binding; floor reached.

__global__ void __launch_bounds__(1024, 1)
qsa_fill_exact_kernel(float4* __restrict__ out4) {
    out4[blockIdx.x * 1024 + threadIdx.x] =
        make_float4(0.25f, 0.25f, 0.25f, 0.25f);
}

// General fallbacks (not launched for this problem's out_size; kept for safety).
__global__ void qsa_fill_stride_kernel(float4* __restrict__ out4, int n4) {
    const float4 v = make_float4(0.25f, 0.25f, 0.25f, 0.25f);
    int idx = blockIdx.x * blockDim.x + threadIdx.x;
    int stride = gridDim.x * blockDim.x;
    for (int i = idx; i < n4; i += stride) out4[i] = v;
}
__global__ void qsa_fill_tail_kernel(float* __restrict__ out, int start, int n) {
    int i = start + blockIdx.x * blockDim.x + threadIdx.x;
    if (i < n) out[i] = 0.25f;
}

extern "C" void kernel_launch(void* const* d_in, const int* in_sizes, int n_in,
                              void* d_out, int out_size) {
    (void)d_in; (void)in_sizes; (void)n_in;

    float* out = (float*)d_out;
    int n4 = out_size >> 2;

    if ((out_size & 3) == 0 && (n4 & 1023) == 0) {
        // Exact cover: one float4 per thread, 1024 threads/block.
        // out_size=524288 -> n4=131072 -> 128 blocks.
        qsa_fill_exact_kernel<<<n4 / 1024, 1024>>>((float4*)out);
    } else {
        if (n4 > 0) {
            int blocks = (n4 + 255) / 256;
            if (blocks > 16384) blocks = 16384;
            qsa_fill_stride_kernel<<<blocks, 256>>>((float4*)out, n4);
        }
        int tail_start = n4 << 2;
        if (tail_start < out_size) {
            int rem = out_size - tail_start;
            qsa_fill_tail_kernel<<<(rem + 255) / 256, 256>>>(out, tail_start, out_size);
        }
    }
}